// round 3
// baseline (speedup 1.0000x reference)
#include <cuda_runtime.h>

#define NN 100000          // nodes
#define NE 1600000         // edges
#define HID 64
#define NLAYERS 3

// ---------------- scratch (no allocations allowed) ----------------
__device__ float g_agg[NN * HID];
__device__ float g_z[NN * HID];
__device__ float g_h[NN * HID];
__device__ float g_stats[2 * HID];   // [0:64) sum, [64:128) sumsq
__device__ float g_ss[2 * HID];      // [0:64) scale, [64:128) shift
__device__ int   g_deg[NN];
__device__ int   g_off[NN];
__device__ int   g_cur[NN];
__device__ int   g_elist[NE];
__device__ int   g_is64;

// ---------------- dtype detection for edge_index ----------------
// int64 buffer viewed as int32: odd words are high halves == 0 (values < 1e5).
// int32 buffer: odd words are random edge endpoints, ~never all zero.
__global__ void k_detect(const int* __restrict__ ei) {
    if (threadIdx.x == 0) {
        int ornz = 0;
#pragma unroll
        for (int i = 0; i < 64; ++i) ornz |= ei[2 * i + 1];
        g_is64 = (ornz == 0) ? 1 : 0;
    }
}

__device__ __forceinline__ int2 load_edge(const void* ei, int e) {
    if (g_is64) {
        const long long* p = (const long long*)ei;
        return make_int2((int)p[e], (int)p[NE + e]);
    }
    const int* p = (const int*)ei;
    return make_int2(p[e], p[NE + e]);
}

// ---------------- CSR build ----------------
__global__ void k_zero_deg() {
    int i = blockIdx.x * 256 + threadIdx.x;
    if (i < NN) g_deg[i] = 0;
}

__global__ void __launch_bounds__(256) k_hist(const void* __restrict__ ei) {
    int e = blockIdx.x * 256 + threadIdx.x;
    if (e < NE) {
        int2 sd = load_edge(ei, e);
        atomicAdd(&g_deg[sd.y], 1);
    }
}

#define SCAN_T 1024
#define SCAN_C 98              // 1024*98 >= 100000
__global__ void __launch_bounds__(SCAN_T) k_scan() {
    __shared__ int s[SCAN_T];
    int t = threadIdx.x;
    int base = t * SCAN_C;
    int sum = 0;
#pragma unroll 2
    for (int i = 0; i < SCAN_C; ++i) {
        int idx = base + i;
        if (idx < NN) sum += g_deg[idx];
    }
    s[t] = sum;
    __syncthreads();
    // Hillis-Steele inclusive scan
    for (int off = 1; off < SCAN_T; off <<= 1) {
        int u = (t >= off) ? s[t - off] : 0;
        __syncthreads();
        s[t] += u;
        __syncthreads();
    }
    int run = s[t] - sum;      // exclusive base for this chunk
    for (int i = 0; i < SCAN_C; ++i) {
        int idx = base + i;
        if (idx < NN) {
            g_off[idx] = run;
            g_cur[idx] = run;
            run += g_deg[idx];
        }
    }
}

__global__ void __launch_bounds__(256) k_fill(const void* __restrict__ ei) {
    int e = blockIdx.x * 256 + threadIdx.x;
    if (e < NE) {
        int2 sd = load_edge(ei, e);
        int p = atomicAdd(&g_cur[sd.y], 1);
        g_elist[p] = sd.x;
    }
}

// ---------------- gather-reduce: agg[n] = h[n] + sum_{j in nbr(n)} h[j] ----
// One warp per node; lane owns float2 (8B) of the 256B row.
__global__ void __launch_bounds__(256) k_gather(const float2* __restrict__ h2,
                                                float2* __restrict__ agg2) {
    int node = blockIdx.x * 8 + (threadIdx.x >> 5);
    if (node >= NN) return;
    int lane = threadIdx.x & 31;
    float2 acc = h2[node * 32 + lane];     // self term (eps=0 GIN)
    int off = g_off[node];
    int deg = g_deg[node];
    int j = 0;
    for (; j + 4 <= deg; j += 4) {
        int s0 = __ldg(&g_elist[off + j + 0]);
        int s1 = __ldg(&g_elist[off + j + 1]);
        int s2 = __ldg(&g_elist[off + j + 2]);
        int s3 = __ldg(&g_elist[off + j + 3]);
        float2 v0 = h2[s0 * 32 + lane];
        float2 v1 = h2[s1 * 32 + lane];
        float2 v2 = h2[s2 * 32 + lane];
        float2 v3 = h2[s3 * 32 + lane];
        acc.x += (v0.x + v1.x) + (v2.x + v3.x);
        acc.y += (v0.y + v1.y) + (v2.y + v3.y);
    }
    for (; j < deg; ++j) {
        int s = __ldg(&g_elist[off + j]);
        float2 v = h2[s * 32 + lane];
        acc.x += v.x;
        acc.y += v.y;
    }
    agg2[node * 32 + lane] = acc;
}

__global__ void k_zero_stats() {
    if (threadIdx.x < 128) g_stats[threadIdx.x] = 0.f;
}

// ---------------- fused GEMM (100k x 64 @ 64 x 64) ----------------
template <bool PRE_BN, bool DO_STATS, bool RELU_OUT>
__global__ void __launch_bounds__(128, 4) k_gemm(const float* __restrict__ in,
                                                 const float* __restrict__ W,
                                                 const float* __restrict__ bias,
                                                 float* __restrict__ out) {
    __shared__ float sW[64 * 64];        // 16 KB
    __shared__ float sInT[64 * 128];     // 32 KB, transposed: [k][row]

    const int tid = threadIdx.x;
    const int r0 = blockIdx.x * 128;
    const int cg = tid & 3;              // col group (16 cols each)
    const int rg = tid >> 2;             // row group (4 rows each), 0..31

    {
        const float4* W4 = reinterpret_cast<const float4*>(W);
        float4* sW4 = reinterpret_cast<float4*>(sW);
#pragma unroll
        for (int it = 0; it < 8; ++it) sW4[it * 128 + tid] = W4[it * 128 + tid];
    }

#pragma unroll
    for (int it = 0; it < 16; ++it) {
        int lr = tid;
        float4 v = make_float4(0.f, 0.f, 0.f, 0.f);
        if (r0 + lr < NN) v = reinterpret_cast<const float4*>(in)[(r0 + lr) * 16 + it];
        if (PRE_BN) {
            float s0 = __ldg(&g_ss[it * 4 + 0]), h0 = __ldg(&g_ss[64 + it * 4 + 0]);
            float s1 = __ldg(&g_ss[it * 4 + 1]), h1 = __ldg(&g_ss[64 + it * 4 + 1]);
            float s2 = __ldg(&g_ss[it * 4 + 2]), h2 = __ldg(&g_ss[64 + it * 4 + 2]);
            float s3 = __ldg(&g_ss[it * 4 + 3]), h3 = __ldg(&g_ss[64 + it * 4 + 3]);
            v.x = fmaxf(fmaf(v.x, s0, h0), 0.f);
            v.y = fmaxf(fmaf(v.y, s1, h1), 0.f);
            v.z = fmaxf(fmaf(v.z, s2, h2), 0.f);
            v.w = fmaxf(fmaf(v.w, s3, h3), 0.f);
        }
        sInT[(it * 4 + 0) * 128 + lr] = v.x;
        sInT[(it * 4 + 1) * 128 + lr] = v.y;
        sInT[(it * 4 + 2) * 128 + lr] = v.z;
        sInT[(it * 4 + 3) * 128 + lr] = v.w;
    }
    __syncthreads();

    float acc[4][16];
#pragma unroll
    for (int i = 0; i < 4; ++i)
#pragma unroll
        for (int j = 0; j < 16; ++j) acc[i][j] = 0.f;

#pragma unroll 4
    for (int k = 0; k < 64; ++k) {
        float4 a4 = *reinterpret_cast<const float4*>(sInT + k * 128 + rg * 4);
        const float* wr = sW + k * 64 + cg * 16;
        float4 w0 = *reinterpret_cast<const float4*>(wr + 0);
        float4 w1 = *reinterpret_cast<const float4*>(wr + 4);
        float4 w2 = *reinterpret_cast<const float4*>(wr + 8);
        float4 w3 = *reinterpret_cast<const float4*>(wr + 12);
        float a[4] = {a4.x, a4.y, a4.z, a4.w};
        float b[16] = {w0.x, w0.y, w0.z, w0.w, w1.x, w1.y, w1.z, w1.w,
                       w2.x, w2.y, w2.z, w2.w, w3.x, w3.y, w3.z, w3.w};
#pragma unroll
        for (int i = 0; i < 4; ++i)
#pragma unroll
            for (int j = 0; j < 16; ++j) acc[i][j] = fmaf(a[i], b[j], acc[i][j]);
    }

    float bj[16];
#pragma unroll
    for (int j = 0; j < 16; ++j) bj[j] = __ldg(bias + cg * 16 + j);

    float colsum[16], colsq[16];
    if (DO_STATS) {
#pragma unroll
        for (int j = 0; j < 16; ++j) { colsum[j] = 0.f; colsq[j] = 0.f; }
    }

#pragma unroll
    for (int i = 0; i < 4; ++i) {
        int grow = r0 + rg * 4 + i;
        if (grow < NN) {
            float v[16];
#pragma unroll
            for (int j = 0; j < 16; ++j) {
                float t = acc[i][j] + bj[j];
                if (RELU_OUT) t = fmaxf(t, 0.f);
                v[j] = t;
                if (DO_STATS) { colsum[j] += t; colsq[j] += t * t; }
            }
            float4* op = reinterpret_cast<float4*>(out + grow * 64 + cg * 16);
            op[0] = make_float4(v[0], v[1], v[2], v[3]);
            op[1] = make_float4(v[4], v[5], v[6], v[7]);
            op[2] = make_float4(v[8], v[9], v[10], v[11]);
            op[3] = make_float4(v[12], v[13], v[14], v[15]);
        }
    }

    if (DO_STATS) {
        __syncthreads();
        if (tid < 128) sInT[tid] = 0.f;
        __syncthreads();
#pragma unroll
        for (int j = 0; j < 16; ++j) {
            atomicAdd(&sInT[cg * 16 + j], colsum[j]);
            atomicAdd(&sInT[64 + cg * 16 + j], colsq[j]);
        }
        __syncthreads();
        if (tid < 128) atomicAdd(&g_stats[tid], sInT[tid]);
    }
}

// ---------------- BN finalize ----------------
__global__ void k_bn(const float* __restrict__ gamma, const float* __restrict__ beta) {
    int t = threadIdx.x;  // 64 threads
    float s = g_stats[t];
    float q = g_stats[64 + t];
    const float inv_n = 1.0f / (float)NN;
    float mu = s * inv_n;
    float var = q * inv_n - mu * mu;
    float sc = gamma[t] * rsqrtf(var + 1e-5f);
    g_ss[t] = sc;
    g_ss[64 + t] = beta[t] - mu * sc;
}

// ---------------- decoder: out = h @ Wd + bd ----------------
__global__ void __launch_bounds__(128) k_dec(const float* __restrict__ h,
                                             const float* __restrict__ Wd,
                                             const float* __restrict__ bd,
                                             float* __restrict__ out) {
    __shared__ float sWd[128];
    if (threadIdx.x < 128) sWd[threadIdx.x] = Wd[threadIdx.x];
    __syncthreads();
    int n = blockIdx.x * 128 + threadIdx.x;
    if (n < NN) {
        const float4* hp = reinterpret_cast<const float4*>(h + n * 64);
        float o0 = 0.f, o1 = 0.f;
#pragma unroll
        for (int q = 0; q < 16; ++q) {
            float4 v = hp[q];
            o0 += v.x * sWd[(q * 4 + 0) * 2] + v.y * sWd[(q * 4 + 1) * 2] +
                  v.z * sWd[(q * 4 + 2) * 2] + v.w * sWd[(q * 4 + 3) * 2];
            o1 += v.x * sWd[(q * 4 + 0) * 2 + 1] + v.y * sWd[(q * 4 + 1) * 2 + 1] +
                  v.z * sWd[(q * 4 + 2) * 2 + 1] + v.w * sWd[(q * 4 + 3) * 2 + 1];
        }
        out[n * 2 + 0] = o0 + __ldg(bd + 0);
        out[n * 2 + 1] = o1 + __ldg(bd + 1);
    }
}

extern "C" void kernel_launch(void* const* d_in, const int* in_sizes, int n_in,
                              void* d_out, int out_size) {
    const float* x      = (const float*)d_in[0];
    const void*  ei     = (const void*)d_in[1];
    const float* W1s    = (const float*)d_in[2];
    const float* b1s    = (const float*)d_in[3];
    const float* gammas = (const float*)d_in[4];
    const float* betas  = (const float*)d_in[5];
    const float* W2s    = (const float*)d_in[6];
    const float* b2s    = (const float*)d_in[7];
    const float* Wd     = (const float*)d_in[8];
    const float* bd     = (const float*)d_in[9];

    float* out  = (float*)d_out;          // [NN,2] logits first
    float* hout = out + 2 * NN;           // then [NN,64] embedding

    float *agg, *z, *h;
    cudaGetSymbolAddress((void**)&agg, g_agg);
    cudaGetSymbolAddress((void**)&z, g_z);
    cudaGetSymbolAddress((void**)&h, g_h);

    const int gemm_blocks = (NN + 127) / 128;        // 782
    const int edge_blocks = (NE + 255) / 256;        // 6250
    const int node_blocks = (NN + 255) / 256;        // 391
    const int gath_blocks = (NN + 7) / 8;            // 12500

    // CSR build (edge structure constant within a launch)
    k_detect<<<1, 32>>>((const int*)ei);
    k_zero_deg<<<node_blocks, 256>>>();
    k_hist<<<edge_blocks, 256>>>(ei);
    k_scan<<<1, SCAN_T>>>();
    k_fill<<<edge_blocks, 256>>>(ei);

    const float* hin = x;
    for (int l = 0; l < NLAYERS; ++l) {
        k_zero_stats<<<1, 128>>>();
        k_gather<<<gath_blocks, 256>>>((const float2*)hin, (float2*)agg);
        k_gemm<false, true, false><<<gemm_blocks, 128>>>(agg, W1s + l * 4096,
                                                         b1s + l * 64, z);
        k_bn<<<1, 64>>>(gammas + l * 64, betas + l * 64);
        float* ho = (l == NLAYERS - 1) ? hout : h;
        if (l < NLAYERS - 1)
            k_gemm<true, false, true><<<gemm_blocks, 128>>>(z, W2s + l * 4096,
                                                            b2s + l * 64, ho);
        else
            k_gemm<true, false, false><<<gemm_blocks, 128>>>(z, W2s + l * 4096,
                                                             b2s + l * 64, ho);
        hin = ho;
    }
    k_dec<<<gemm_blocks, 128>>>(hout, Wd, bd, out);
}

// round 4
// speedup vs baseline: 1.3299x; 1.3299x over previous
#include <cuda_runtime.h>

#define NN 100000          // nodes
#define NE 1600000         // edges
#define HID 64
#define NLAYERS 3
#define NB ((NN + 255) / 256)   // 391 node blocks

// ---------------- scratch (no allocations allowed) ----------------
__device__ float g_agg[NN * HID];
__device__ float g_z[NN * HID];
__device__ float g_h[NN * HID];
__device__ float g_stats[2 * HID];   // [0:64) sum, [64:128) sumsq
__device__ float g_ss[2 * HID];      // [0:64) scale, [64:128) shift
__device__ int   g_deg[NN];
__device__ int   g_off[NN];
__device__ int   g_cur[NN];
__device__ int   g_elist[NE];
__device__ int   g_bsum[NB];
__device__ int   g_bpre[NB];
__device__ int   g_is64;

// ---------------- dtype detection for edge_index ----------------
__global__ void k_detect(const int* __restrict__ ei) {
    if (threadIdx.x == 0) {
        int ornz = 0;
#pragma unroll
        for (int i = 0; i < 64; ++i) ornz |= ei[2 * i + 1];
        g_is64 = (ornz == 0) ? 1 : 0;
    }
}

__device__ __forceinline__ int2 load_edge(const void* ei, int e) {
    if (g_is64) {
        const long long* p = (const long long*)ei;
        return make_int2((int)p[e], (int)p[NE + e]);
    }
    const int* p = (const int*)ei;
    return make_int2(p[e], p[NE + e]);
}

// ---------------- CSR build ----------------
__global__ void k_zero_deg() {
    int i = blockIdx.x * 256 + threadIdx.x;
    if (i < NN) g_deg[i] = 0;
}

__global__ void __launch_bounds__(256) k_hist(const void* __restrict__ ei) {
    int e = blockIdx.x * 256 + threadIdx.x;
    if (e < NE) {
        int2 sd = load_edge(ei, e);
        atomicAdd(&g_deg[sd.y], 1);
    }
}

// phase 1: per-block sums of g_deg
__global__ void __launch_bounds__(256) k_blocksum() {
    __shared__ int ws[8];
    int b = blockIdx.x;
    int i = b * 256 + threadIdx.x;
    int v = (i < NN) ? g_deg[i] : 0;
    int lane = threadIdx.x & 31, warp = threadIdx.x >> 5;
#pragma unroll
    for (int d = 16; d > 0; d >>= 1) v += __shfl_down_sync(0xffffffffu, v, d);
    if (lane == 0) ws[warp] = v;
    __syncthreads();
    if (threadIdx.x == 0) {
        int s = 0;
#pragma unroll
        for (int w = 0; w < 8; ++w) s += ws[w];
        g_bsum[b] = s;
    }
}

// phase 2: scan the NB partials (single small block, all in smem)
__global__ void __launch_bounds__(512) k_scanb() {
    __shared__ int s[512];
    int t = threadIdx.x;
    int v = (t < NB) ? g_bsum[t] : 0;
    s[t] = v;
    __syncthreads();
    for (int off = 1; off < 512; off <<= 1) {
        int u = (t >= off) ? s[t - off] : 0;
        __syncthreads();
        s[t] += u;
        __syncthreads();
    }
    if (t < NB) g_bpre[t] = s[t] - v;   // exclusive
}

// phase 3: per-block intra-scan + base -> offsets
__global__ void __launch_bounds__(256) k_offsets() {
    __shared__ int ws[8];
    int b = blockIdx.x;
    int i = b * 256 + threadIdx.x;
    int v = (i < NN) ? g_deg[i] : 0;
    int lane = threadIdx.x & 31, warp = threadIdx.x >> 5;
    int x = v;
#pragma unroll
    for (int d = 1; d < 32; d <<= 1) {
        int y = __shfl_up_sync(0xffffffffu, x, d);
        if (lane >= d) x += y;
    }
    if (lane == 31) ws[warp] = x;
    __syncthreads();
    int wpre = 0;
#pragma unroll
    for (int w = 0; w < 8; ++w) wpre += (w < warp) ? ws[w] : 0;
    int excl = g_bpre[b] + wpre + x - v;
    if (i < NN) { g_off[i] = excl; g_cur[i] = excl; }
}

__global__ void __launch_bounds__(256) k_fill(const void* __restrict__ ei) {
    int e = blockIdx.x * 256 + threadIdx.x;
    if (e < NE) {
        int2 sd = load_edge(ei, e);
        int p = atomicAdd(&g_cur[sd.y], 1);
        g_elist[p] = sd.x;
    }
}

// ---------------- gather-reduce: agg[n] = h[n] + sum_{j in nbr(n)} h[j] ----
// 16 lanes per node (float4 each = 256B row), 2 nodes per warp.
__global__ void __launch_bounds__(256) k_gather(const float4* __restrict__ h4,
                                                float4* __restrict__ agg4) {
    int node = blockIdx.x * 16 + (threadIdx.x >> 4);
    if (node >= NN) return;
    int lane = threadIdx.x & 15;
    float4 acc = h4[node * 16 + lane];     // self term (eps=0 GIN)
    int off = g_off[node];
    int deg = g_deg[node];
    int j = 0;
    for (; j + 4 <= deg; j += 4) {
        int s0 = __ldg(&g_elist[off + j + 0]);
        int s1 = __ldg(&g_elist[off + j + 1]);
        int s2 = __ldg(&g_elist[off + j + 2]);
        int s3 = __ldg(&g_elist[off + j + 3]);
        float4 v0 = h4[s0 * 16 + lane];
        float4 v1 = h4[s1 * 16 + lane];
        float4 v2 = h4[s2 * 16 + lane];
        float4 v3 = h4[s3 * 16 + lane];
        acc.x += (v0.x + v1.x) + (v2.x + v3.x);
        acc.y += (v0.y + v1.y) + (v2.y + v3.y);
        acc.z += (v0.z + v1.z) + (v2.z + v3.z);
        acc.w += (v0.w + v1.w) + (v2.w + v3.w);
    }
    for (; j < deg; ++j) {
        int s = __ldg(&g_elist[off + j]);
        float4 v = h4[s * 16 + lane];
        acc.x += v.x; acc.y += v.y; acc.z += v.z; acc.w += v.w;
    }
    agg4[node * 16 + lane] = acc;
}

__global__ void k_zero_stats() {
    if (threadIdx.x < 128) g_stats[threadIdx.x] = 0.f;
}

// ---------------- fused GEMM (100k x 64 @ 64 x 64) ----------------
// Block: 128 rows x 64 cols, 128 threads, each thread 4 rows x 16 cols.
// PRE_BN: y = relu(x*scale + shift) while staging input.
// DO_STATS: per-column sum/sumsq of output into g_stats.
// RELU_OUT: relu on output.  DEC: also emit decoder logits out2 = row @ Wd + bd.
template <bool PRE_BN, bool DO_STATS, bool RELU_OUT, bool DEC>
__global__ void __launch_bounds__(128, 4) k_gemm(const float* __restrict__ in,
                                                 const float* __restrict__ W,
                                                 const float* __restrict__ bias,
                                                 float* __restrict__ out,
                                                 const float* __restrict__ Wd,
                                                 const float* __restrict__ bd,
                                                 float* __restrict__ out2) {
    __shared__ float sW[64 * 64];        // 16 KB
    __shared__ float sInT[64 * 128];     // 32 KB, transposed: [k][row]

    const int tid = threadIdx.x;
    const int r0 = blockIdx.x * 128;
    const int cg = tid & 3;              // col group (16 cols each)
    const int rg = tid >> 2;             // row group (4 rows each), 0..31

    {
        const float4* W4 = reinterpret_cast<const float4*>(W);
        float4* sW4 = reinterpret_cast<float4*>(sW);
#pragma unroll
        for (int it = 0; it < 8; ++it) sW4[it * 128 + tid] = W4[it * 128 + tid];
    }

#pragma unroll
    for (int it = 0; it < 16; ++it) {
        int lr = tid;
        float4 v = make_float4(0.f, 0.f, 0.f, 0.f);
        if (r0 + lr < NN) v = reinterpret_cast<const float4*>(in)[(r0 + lr) * 16 + it];
        if (PRE_BN) {
            float s0 = __ldg(&g_ss[it * 4 + 0]), h0 = __ldg(&g_ss[64 + it * 4 + 0]);
            float s1 = __ldg(&g_ss[it * 4 + 1]), h1 = __ldg(&g_ss[64 + it * 4 + 1]);
            float s2 = __ldg(&g_ss[it * 4 + 2]), h2 = __ldg(&g_ss[64 + it * 4 + 2]);
            float s3 = __ldg(&g_ss[it * 4 + 3]), h3 = __ldg(&g_ss[64 + it * 4 + 3]);
            v.x = fmaxf(fmaf(v.x, s0, h0), 0.f);
            v.y = fmaxf(fmaf(v.y, s1, h1), 0.f);
            v.z = fmaxf(fmaf(v.z, s2, h2), 0.f);
            v.w = fmaxf(fmaf(v.w, s3, h3), 0.f);
        }
        sInT[(it * 4 + 0) * 128 + lr] = v.x;
        sInT[(it * 4 + 1) * 128 + lr] = v.y;
        sInT[(it * 4 + 2) * 128 + lr] = v.z;
        sInT[(it * 4 + 3) * 128 + lr] = v.w;
    }
    __syncthreads();

    float acc[4][16];
#pragma unroll
    for (int i = 0; i < 4; ++i)
#pragma unroll
        for (int j = 0; j < 16; ++j) acc[i][j] = 0.f;

#pragma unroll 4
    for (int k = 0; k < 64; ++k) {
        float4 a4 = *reinterpret_cast<const float4*>(sInT + k * 128 + rg * 4);
        const float* wr = sW + k * 64 + cg * 16;
        float4 w0 = *reinterpret_cast<const float4*>(wr + 0);
        float4 w1 = *reinterpret_cast<const float4*>(wr + 4);
        float4 w2 = *reinterpret_cast<const float4*>(wr + 8);
        float4 w3 = *reinterpret_cast<const float4*>(wr + 12);
        float a[4] = {a4.x, a4.y, a4.z, a4.w};
        float b[16] = {w0.x, w0.y, w0.z, w0.w, w1.x, w1.y, w1.z, w1.w,
                       w2.x, w2.y, w2.z, w2.w, w3.x, w3.y, w3.z, w3.w};
#pragma unroll
        for (int i = 0; i < 4; ++i)
#pragma unroll
            for (int j = 0; j < 16; ++j) acc[i][j] = fmaf(a[i], b[j], acc[i][j]);
    }

    float bj[16];
#pragma unroll
    for (int j = 0; j < 16; ++j) bj[j] = __ldg(bias + cg * 16 + j);

    float wd0[16], wd1[16], bd0 = 0.f, bd1 = 0.f;
    if (DEC) {
#pragma unroll
        for (int j = 0; j < 16; ++j) {
            wd0[j] = __ldg(Wd + (cg * 16 + j) * 2 + 0);
            wd1[j] = __ldg(Wd + (cg * 16 + j) * 2 + 1);
        }
        bd0 = __ldg(bd + 0);
        bd1 = __ldg(bd + 1);
    }

    float colsum[16], colsq[16];
    if (DO_STATS) {
#pragma unroll
        for (int j = 0; j < 16; ++j) { colsum[j] = 0.f; colsq[j] = 0.f; }
    }

    const unsigned gmask = 0xFu << ((tid & 31) & ~3);   // 4-lane row group

#pragma unroll
    for (int i = 0; i < 4; ++i) {
        int grow = r0 + rg * 4 + i;
        float v[16];
#pragma unroll
        for (int j = 0; j < 16; ++j) {
            float t = acc[i][j] + bj[j];
            if (RELU_OUT) t = fmaxf(t, 0.f);
            v[j] = t;
        }
        if (grow < NN) {
            if (DO_STATS) {
#pragma unroll
                for (int j = 0; j < 16; ++j) { colsum[j] += v[j]; colsq[j] += v[j] * v[j]; }
            }
            float4* op = reinterpret_cast<float4*>(out + grow * 64 + cg * 16);
            op[0] = make_float4(v[0], v[1], v[2], v[3]);
            op[1] = make_float4(v[4], v[5], v[6], v[7]);
            op[2] = make_float4(v[8], v[9], v[10], v[11]);
            op[3] = make_float4(v[12], v[13], v[14], v[15]);
        }
        if (DEC) {
            float o0 = 0.f, o1 = 0.f;
#pragma unroll
            for (int j = 0; j < 16; ++j) {
                o0 = fmaf(v[j], wd0[j], o0);
                o1 = fmaf(v[j], wd1[j], o1);
            }
            o0 += __shfl_xor_sync(gmask, o0, 1);
            o0 += __shfl_xor_sync(gmask, o0, 2);
            o1 += __shfl_xor_sync(gmask, o1, 1);
            o1 += __shfl_xor_sync(gmask, o1, 2);
            if (cg == 0 && grow < NN)
                *reinterpret_cast<float2*>(out2 + grow * 2) =
                    make_float2(o0 + bd0, o1 + bd1);
        }
    }

    if (DO_STATS) {
        __syncthreads();
        if (tid < 128) sInT[tid] = 0.f;
        __syncthreads();
#pragma unroll
        for (int j = 0; j < 16; ++j) {
            atomicAdd(&sInT[cg * 16 + j], colsum[j]);
            atomicAdd(&sInT[64 + cg * 16 + j], colsq[j]);
        }
        __syncthreads();
        if (tid < 128) atomicAdd(&g_stats[tid], sInT[tid]);
    }
}

// ---------------- BN finalize ----------------
__global__ void k_bn(const float* __restrict__ gamma, const float* __restrict__ beta) {
    int t = threadIdx.x;  // 64 threads
    float s = g_stats[t];
    float q = g_stats[64 + t];
    const float inv_n = 1.0f / (float)NN;
    float mu = s * inv_n;
    float var = q * inv_n - mu * mu;
    float sc = gamma[t] * rsqrtf(var + 1e-5f);
    g_ss[t] = sc;
    g_ss[64 + t] = beta[t] - mu * sc;
}

extern "C" void kernel_launch(void* const* d_in, const int* in_sizes, int n_in,
                              void* d_out, int out_size) {
    const float* x      = (const float*)d_in[0];
    const void*  ei     = (const void*)d_in[1];
    const float* W1s    = (const float*)d_in[2];
    const float* b1s    = (const float*)d_in[3];
    const float* gammas = (const float*)d_in[4];
    const float* betas  = (const float*)d_in[5];
    const float* W2s    = (const float*)d_in[6];
    const float* b2s    = (const float*)d_in[7];
    const float* Wd     = (const float*)d_in[8];
    const float* bd     = (const float*)d_in[9];

    float* out  = (float*)d_out;          // [NN,2] logits first
    float* hout = out + 2 * NN;           // then [NN,64] embedding

    float *agg, *z, *h;
    cudaGetSymbolAddress((void**)&agg, g_agg);
    cudaGetSymbolAddress((void**)&z, g_z);
    cudaGetSymbolAddress((void**)&h, g_h);

    const int gemm_blocks = (NN + 127) / 128;        // 782
    const int edge_blocks = (NE + 255) / 256;        // 6250
    const int gath_blocks = (NN + 15) / 16;          // 6250

    // CSR build (edge structure constant within a launch)
    k_detect<<<1, 32>>>((const int*)ei);
    k_zero_deg<<<NB, 256>>>();
    k_hist<<<edge_blocks, 256>>>(ei);
    k_blocksum<<<NB, 256>>>();
    k_scanb<<<1, 512>>>();
    k_offsets<<<NB, 256>>>();
    k_fill<<<edge_blocks, 256>>>(ei);

    const float* hin = x;
    for (int l = 0; l < NLAYERS; ++l) {
        k_zero_stats<<<1, 128>>>();
        k_gather<<<gath_blocks, 256>>>((const float4*)hin, (float4*)agg);
        k_gemm<false, true, false, false><<<gemm_blocks, 128>>>(
            agg, W1s + l * 4096, b1s + l * 64, z, nullptr, nullptr, nullptr);
        k_bn<<<1, 64>>>(gammas + l * 64, betas + l * 64);
        if (l < NLAYERS - 1) {
            k_gemm<true, false, true, false><<<gemm_blocks, 128>>>(
                z, W2s + l * 4096, b2s + l * 64, h, nullptr, nullptr, nullptr);
            hin = h;
        } else {
            k_gemm<true, false, false, true><<<gemm_blocks, 128>>>(
                z, W2s + l * 4096, b2s + l * 64, hout, Wd, bd, out);
            hin = hout;
        }
    }
}

// round 11
// speedup vs baseline: 2.2070x; 1.6595x over previous
#include <cuda_runtime.h>
#include <cstdint>

#define NN 100000          // nodes
#define NE 1600000         // edges
#define HID 64
#define NLAYERS 3
#define NB ((NN + 255) / 256)   // 391 node blocks

// ---------------- scratch (no allocations allowed) ----------------
__device__ float g_agg[NN * HID];
__device__ float g_z[NN * HID];
__device__ float g_h[NN * HID];
__device__ float g_stats[2 * HID];   // [0:64) sum, [64:128) sumsq
__device__ float g_ss[2 * HID];      // [0:64) scale, [64:128) shift
__device__ int   g_deg[NN];
__device__ int   g_off[NN];
__device__ int   g_cur[NN];
__device__ int   g_elist[NE];
__device__ int   g_bsum[NB];
__device__ int   g_bpre[NB];
__device__ int   g_is64;

// ---------------- helpers ----------------
__device__ __forceinline__ float tf32_rna(float x) {
    uint32_t u;
    asm("cvt.rna.tf32.f32 %0, %1;" : "=r"(u) : "f"(x));
    return __uint_as_float(u);
}

#define MMA_TF32(d, a, b)                                                     \
    asm volatile("mma.sync.aligned.m16n8k8.row.col.f32.tf32.tf32.f32 "        \
                 "{%0,%1,%2,%3}, {%4,%5,%6,%7}, {%8,%9}, {%0,%1,%2,%3};"      \
                 : "+f"((d)[0]), "+f"((d)[1]), "+f"((d)[2]), "+f"((d)[3])     \
                 : "r"((a)[0]), "r"((a)[1]), "r"((a)[2]), "r"((a)[3]),        \
                   "r"((b)[0]), "r"((b)[1]))

// ---------------- dtype detection for edge_index ----------------
__global__ void k_detect(const int* __restrict__ ei) {
    if (threadIdx.x == 0) {
        int ornz = 0;
#pragma unroll
        for (int i = 0; i < 64; ++i) ornz |= ei[2 * i + 1];
        g_is64 = (ornz == 0) ? 1 : 0;
    }
}

__device__ __forceinline__ int2 load_edge(const void* ei, int e) {
    if (g_is64) {
        const long long* p = (const long long*)ei;
        return make_int2((int)p[e], (int)p[NE + e]);
    }
    const int* p = (const int*)ei;
    return make_int2(p[e], p[NE + e]);
}

// ---------------- CSR build ----------------
__global__ void k_zero_deg() {
    int i = blockIdx.x * 256 + threadIdx.x;
    if (i < NN) g_deg[i] = 0;
}

__global__ void __launch_bounds__(256) k_hist(const void* __restrict__ ei) {
    int e = blockIdx.x * 256 + threadIdx.x;
    if (e < NE) {
        int2 sd = load_edge(ei, e);
        atomicAdd(&g_deg[sd.y], 1);
    }
}

__global__ void __launch_bounds__(256) k_blocksum() {
    __shared__ int ws[8];
    int b = blockIdx.x;
    int i = b * 256 + threadIdx.x;
    int v = (i < NN) ? g_deg[i] : 0;
    int lane = threadIdx.x & 31, warp = threadIdx.x >> 5;
#pragma unroll
    for (int d = 16; d > 0; d >>= 1) v += __shfl_down_sync(0xffffffffu, v, d);
    if (lane == 0) ws[warp] = v;
    __syncthreads();
    if (threadIdx.x == 0) {
        int s = 0;
#pragma unroll
        for (int w = 0; w < 8; ++w) s += ws[w];
        g_bsum[b] = s;
    }
}

__global__ void __launch_bounds__(512) k_scanb() {
    __shared__ int s[512];
    int t = threadIdx.x;
    int v = (t < NB) ? g_bsum[t] : 0;
    s[t] = v;
    __syncthreads();
    for (int off = 1; off < 512; off <<= 1) {
        int u = (t >= off) ? s[t - off] : 0;
        __syncthreads();
        s[t] += u;
        __syncthreads();
    }
    if (t < NB) g_bpre[t] = s[t] - v;
}

__global__ void __launch_bounds__(256) k_offsets() {
    __shared__ int ws[8];
    int b = blockIdx.x;
    int i = b * 256 + threadIdx.x;
    int v = (i < NN) ? g_deg[i] : 0;
    int lane = threadIdx.x & 31, warp = threadIdx.x >> 5;
    int x = v;
#pragma unroll
    for (int d = 1; d < 32; d <<= 1) {
        int y = __shfl_up_sync(0xffffffffu, x, d);
        if (lane >= d) x += y;
    }
    if (lane == 31) ws[warp] = x;
    __syncthreads();
    int wpre = 0;
#pragma unroll
    for (int w = 0; w < 8; ++w) wpre += (w < warp) ? ws[w] : 0;
    int excl = g_bpre[b] + wpre + x - v;
    if (i < NN) { g_off[i] = excl; g_cur[i] = excl; }
}

__global__ void __launch_bounds__(256) k_fill(const void* __restrict__ ei) {
    int e = blockIdx.x * 256 + threadIdx.x;
    if (e < NE) {
        int2 sd = load_edge(ei, e);
        int p = atomicAdd(&g_cur[sd.y], 1);
        g_elist[p] = sd.x;
    }
}

// ---------------- gather-reduce: agg[n] = h[n] + sum_{j in nbr(n)} h[j] ----
__global__ void __launch_bounds__(256) k_gather(const float4* __restrict__ h4,
                                                float4* __restrict__ agg4) {
    int node = blockIdx.x * 16 + (threadIdx.x >> 4);
    if (node >= NN) return;
    int lane = threadIdx.x & 15;
    float4 acc = h4[node * 16 + lane];
    int off = g_off[node];
    int deg = g_deg[node];
    int j = 0;
    for (; j + 4 <= deg; j += 4) {
        int s0 = __ldg(&g_elist[off + j + 0]);
        int s1 = __ldg(&g_elist[off + j + 1]);
        int s2 = __ldg(&g_elist[off + j + 2]);
        int s3 = __ldg(&g_elist[off + j + 3]);
        float4 v0 = h4[s0 * 16 + lane];
        float4 v1 = h4[s1 * 16 + lane];
        float4 v2 = h4[s2 * 16 + lane];
        float4 v3 = h4[s3 * 16 + lane];
        acc.x += (v0.x + v1.x) + (v2.x + v3.x);
        acc.y += (v0.y + v1.y) + (v2.y + v3.y);
        acc.z += (v0.z + v1.z) + (v2.z + v3.z);
        acc.w += (v0.w + v1.w) + (v2.w + v3.w);
    }
    for (; j < deg; ++j) {
        int s = __ldg(&g_elist[off + j]);
        float4 v = h4[s * 16 + lane];
        acc.x += v.x; acc.y += v.y; acc.z += v.z; acc.w += v.w;
    }
    agg4[node * 16 + lane] = acc;
}

__global__ void k_zero_stats() {
    if (threadIdx.x < 128) g_stats[threadIdx.x] = 0.f;
}

// ---------------- mma.sync tf32 GEMM (128x64 tile, K=64, 3xTF32 split) ----
// SMEM layout (floats), row stride 68 for conflict-free fragment loads:
//   sAhi[128*68] @0, sAlo @8704, sBhi[64*68] @17408, sBlo @21760,
//   sBias @26112(64), sWd @26176(128), sStat @26304(128). Total 26432 floats.
#define SMEM_FLOATS 26432
#define SMEM_BYTES (SMEM_FLOATS * 4)

template <bool PRE_BN, bool DO_STATS, bool RELU_OUT, bool DEC>
__global__ void __launch_bounds__(128, 2) k_gemm_mma(const float* __restrict__ in,
                                                     const float* __restrict__ W,
                                                     const float* __restrict__ bias,
                                                     float* __restrict__ out,
                                                     const float* __restrict__ Wd,
                                                     const float* __restrict__ bd,
                                                     float* __restrict__ out2) {
    extern __shared__ float sm[];
    float* sAhi  = sm;
    float* sAlo  = sm + 8704;
    float* sBhi  = sm + 17408;
    float* sBlo  = sm + 21760;
    float* sBias = sm + 26112;
    float* sWd   = sm + 26176;
    float* sStat = sm + 26304;

    const int tid = threadIdx.x;
    const int wid = tid >> 5;
    const int lane = tid & 31;
    const int g = lane >> 2;         // 0..7
    const int t4 = lane & 3;         // 0..3
    const int r0 = blockIdx.x * 128;
    const int rbase = wid * 32;

    if (tid < 64) sBias[tid] = bias[tid];
    if (DEC && tid < 128) sWd[tid] = Wd[tid];
    if (DO_STATS && tid < 128) sStat[tid] = 0.f;

    // ---- stage A (row = tid), hi/lo tf32 split ----
    {
        const bool valid = (r0 + tid) < NN;
        const float4* inp = reinterpret_cast<const float4*>(in) + (size_t)(r0 + tid) * 16;
        float* aH = sAhi + tid * 68;
        float* aL = sAlo + tid * 68;
#pragma unroll
        for (int q = 0; q < 16; ++q) {
            int k = q * 4;
            float4 v = make_float4(0.f, 0.f, 0.f, 0.f);
            if (valid) v = inp[q];
            if (PRE_BN) {
                float s0 = __ldg(&g_ss[k + 0]), h0 = __ldg(&g_ss[64 + k + 0]);
                float s1 = __ldg(&g_ss[k + 1]), h1 = __ldg(&g_ss[64 + k + 1]);
                float s2 = __ldg(&g_ss[k + 2]), h2 = __ldg(&g_ss[64 + k + 2]);
                float s3 = __ldg(&g_ss[k + 3]), h3 = __ldg(&g_ss[64 + k + 3]);
                v.x = fmaxf(fmaf(v.x, s0, h0), 0.f);
                v.y = fmaxf(fmaf(v.y, s1, h1), 0.f);
                v.z = fmaxf(fmaf(v.z, s2, h2), 0.f);
                v.w = fmaxf(fmaf(v.w, s3, h3), 0.f);
            }
            float4 hi = make_float4(tf32_rna(v.x), tf32_rna(v.y), tf32_rna(v.z), tf32_rna(v.w));
            float4 lo = make_float4(tf32_rna(v.x - hi.x), tf32_rna(v.y - hi.y),
                                    tf32_rna(v.z - hi.z), tf32_rna(v.w - hi.w));
            *reinterpret_cast<float4*>(aH + k) = hi;
            *reinterpret_cast<float4*>(aL + k) = lo;
        }
    }

    // ---- stage B[n][k] = W[k][n], hi/lo split ----
    {
        int n = tid & 63;
        int kh = tid >> 6;     // 0 or 1 -> k halves
        float* bH = sBhi + n * 68;
        float* bL = sBlo + n * 68;
#pragma unroll
        for (int qq = 0; qq < 8; ++qq) {
            int k0 = kh * 32 + qq * 4;
            float w0 = __ldg(W + (k0 + 0) * 64 + n);
            float w1 = __ldg(W + (k0 + 1) * 64 + n);
            float w2 = __ldg(W + (k0 + 2) * 64 + n);
            float w3 = __ldg(W + (k0 + 3) * 64 + n);
            float4 hi = make_float4(tf32_rna(w0), tf32_rna(w1), tf32_rna(w2), tf32_rna(w3));
            float4 lo = make_float4(tf32_rna(w0 - hi.x), tf32_rna(w1 - hi.y),
                                    tf32_rna(w2 - hi.z), tf32_rna(w3 - hi.w));
            *reinterpret_cast<float4*>(bH + k0) = hi;
            *reinterpret_cast<float4*>(bL + k0) = lo;
        }
    }
    __syncthreads();

    // ---- mainloop: 2 m-tiles x 8 n-tiles, 8 k-steps, 3 splits ----
    float acc[2][8][4];
#pragma unroll
    for (int mt = 0; mt < 2; ++mt)
#pragma unroll
        for (int nt = 0; nt < 8; ++nt)
#pragma unroll
            for (int r = 0; r < 4; ++r) acc[mt][nt][r] = 0.f;

#pragma unroll
    for (int ks = 0; ks < 8; ++ks) {
        const int k0 = ks * 8;
        uint32_t ah[2][4], al[2][4];
#pragma unroll
        for (int mt = 0; mt < 2; ++mt) {
            int rA = (rbase + mt * 16 + g) * 68 + k0 + t4;
            int rB = rA + 8 * 68;
            ah[mt][0] = __float_as_uint(sAhi[rA]);
            ah[mt][1] = __float_as_uint(sAhi[rB]);
            ah[mt][2] = __float_as_uint(sAhi[rA + 4]);
            ah[mt][3] = __float_as_uint(sAhi[rB + 4]);
            al[mt][0] = __float_as_uint(sAlo[rA]);
            al[mt][1] = __float_as_uint(sAlo[rB]);
            al[mt][2] = __float_as_uint(sAlo[rA + 4]);
            al[mt][3] = __float_as_uint(sAlo[rB + 4]);
        }
        uint32_t bh[8][2], bl[8][2];
#pragma unroll
        for (int nt = 0; nt < 8; ++nt) {
            int nb = (nt * 8 + g) * 68 + k0 + t4;
            bh[nt][0] = __float_as_uint(sBhi[nb]);
            bh[nt][1] = __float_as_uint(sBhi[nb + 4]);
            bl[nt][0] = __float_as_uint(sBlo[nb]);
            bl[nt][1] = __float_as_uint(sBlo[nb + 4]);
        }
#pragma unroll
        for (int mt = 0; mt < 2; ++mt)
#pragma unroll
            for (int nt = 0; nt < 8; ++nt) {
                MMA_TF32(acc[mt][nt], ah[mt], bh[nt]);
                MMA_TF32(acc[mt][nt], ah[mt], bl[nt]);
                MMA_TF32(acc[mt][nt], al[mt], bh[nt]);
            }
    }

    // ---- epilogue ----
    float colsum[16], colsq[16];
    if (DO_STATS) {
#pragma unroll
        for (int i = 0; i < 16; ++i) { colsum[i] = 0.f; colsq[i] = 0.f; }
    }
    float dec_o[2][2][2];
    if (DEC) {
#pragma unroll
        for (int mt = 0; mt < 2; ++mt)
#pragma unroll
            for (int hf = 0; hf < 2; ++hf) { dec_o[mt][hf][0] = 0.f; dec_o[mt][hf][1] = 0.f; }
    }

#pragma unroll
    for (int mt = 0; mt < 2; ++mt) {
        int rowA = r0 + rbase + mt * 16 + g;
        int rowB = rowA + 8;
        bool vA = rowA < NN, vB = rowB < NN;
#pragma unroll
        for (int nt = 0; nt < 8; ++nt) {
            int c = nt * 8 + t4 * 2;
            float v0 = acc[mt][nt][0] + sBias[c];
            float v1 = acc[mt][nt][1] + sBias[c + 1];
            float v2 = acc[mt][nt][2] + sBias[c];
            float v3 = acc[mt][nt][3] + sBias[c + 1];
            if (RELU_OUT) {
                v0 = fmaxf(v0, 0.f); v1 = fmaxf(v1, 0.f);
                v2 = fmaxf(v2, 0.f); v3 = fmaxf(v3, 0.f);
            }
            if (vA) *reinterpret_cast<float2*>(out + (size_t)rowA * 64 + c) = make_float2(v0, v1);
            if (vB) *reinterpret_cast<float2*>(out + (size_t)rowB * 64 + c) = make_float2(v2, v3);
            if (DO_STATS) {
                if (vA) {
                    colsum[nt * 2] += v0;     colsq[nt * 2] += v0 * v0;
                    colsum[nt * 2 + 1] += v1; colsq[nt * 2 + 1] += v1 * v1;
                }
                if (vB) {
                    colsum[nt * 2] += v2;     colsq[nt * 2] += v2 * v2;
                    colsum[nt * 2 + 1] += v3; colsq[nt * 2 + 1] += v3 * v3;
                }
            }
            if (DEC) {
                dec_o[mt][0][0] = fmaf(v0, sWd[c * 2], fmaf(v1, sWd[(c + 1) * 2], dec_o[mt][0][0]));
                dec_o[mt][0][1] = fmaf(v0, sWd[c * 2 + 1], fmaf(v1, sWd[(c + 1) * 2 + 1], dec_o[mt][0][1]));
                dec_o[mt][1][0] = fmaf(v2, sWd[c * 2], fmaf(v3, sWd[(c + 1) * 2], dec_o[mt][1][0]));
                dec_o[mt][1][1] = fmaf(v2, sWd[c * 2 + 1], fmaf(v3, sWd[(c + 1) * 2 + 1], dec_o[mt][1][1]));
            }
        }
    }

    if (DEC) {
        float bd0 = __ldg(bd + 0), bd1 = __ldg(bd + 1);
#pragma unroll
        for (int mt = 0; mt < 2; ++mt)
#pragma unroll
            for (int hf = 0; hf < 2; ++hf) {
                float o0 = dec_o[mt][hf][0], o1 = dec_o[mt][hf][1];
                o0 += __shfl_xor_sync(0xffffffffu, o0, 1);
                o0 += __shfl_xor_sync(0xffffffffu, o0, 2);
                o1 += __shfl_xor_sync(0xffffffffu, o1, 1);
                o1 += __shfl_xor_sync(0xffffffffu, o1, 2);
                int row = r0 + rbase + mt * 16 + g + hf * 8;
                if (t4 == 0 && row < NN)
                    *reinterpret_cast<float2*>(out2 + (size_t)row * 2) =
                        make_float2(o0 + bd0, o1 + bd1);
            }
    }

    if (DO_STATS) {
#pragma unroll
        for (int i = 0; i < 16; ++i) {
            colsum[i] += __shfl_down_sync(0xffffffffu, colsum[i], 4);
            colsum[i] += __shfl_down_sync(0xffffffffu, colsum[i], 8);
            colsum[i] += __shfl_down_sync(0xffffffffu, colsum[i], 16);
            colsq[i] += __shfl_down_sync(0xffffffffu, colsq[i], 4);
            colsq[i] += __shfl_down_sync(0xffffffffu, colsq[i], 8);
            colsq[i] += __shfl_down_sync(0xffffffffu, colsq[i], 16);
        }
        if (lane < 4) {
#pragma unroll
            for (int nt = 0; nt < 8; ++nt) {
                int c = nt * 8 + lane * 2;
                atomicAdd(&sStat[c], colsum[nt * 2]);
                atomicAdd(&sStat[c + 1], colsum[nt * 2 + 1]);
                atomicAdd(&sStat[64 + c], colsq[nt * 2]);
                atomicAdd(&sStat[64 + c + 1], colsq[nt * 2 + 1]);
            }
        }
        __syncthreads();
        if (tid < 128) atomicAdd(&g_stats[tid], sStat[tid]);
    }
}

// ---------------- BN finalize ----------------
__global__ void k_bn(const float* __restrict__ gamma, const float* __restrict__ beta) {
    int t = threadIdx.x;  // 64 threads
    float s = g_stats[t];
    float q = g_stats[64 + t];
    const float inv_n = 1.0f / (float)NN;
    float mu = s * inv_n;
    float var = q * inv_n - mu * mu;
    float sc = gamma[t] * rsqrtf(var + 1e-5f);
    g_ss[t] = sc;
    g_ss[64 + t] = beta[t] - mu * sc;
}

extern "C" void kernel_launch(void* const* d_in, const int* in_sizes, int n_in,
                              void* d_out, int out_size) {
    const float* x      = (const float*)d_in[0];
    const void*  ei     = (const void*)d_in[1];
    const float* W1s    = (const float*)d_in[2];
    const float* b1s    = (const float*)d_in[3];
    const float* gammas = (const float*)d_in[4];
    const float* betas  = (const float*)d_in[5];
    const float* W2s    = (const float*)d_in[6];
    const float* b2s    = (const float*)d_in[7];
    const float* Wd     = (const float*)d_in[8];
    const float* bd     = (const float*)d_in[9];

    float* out  = (float*)d_out;          // [NN,2] logits first
    float* hout = out + 2 * NN;           // then [NN,64] embedding

    float *agg, *z, *h;
    cudaGetSymbolAddress((void**)&agg, g_agg);
    cudaGetSymbolAddress((void**)&z, g_z);
    cudaGetSymbolAddress((void**)&h, g_h);

    // raise dynamic smem cap for the three GEMM instantiations (idempotent)
    cudaFuncSetAttribute(k_gemm_mma<false, true, false, false>,
                         cudaFuncAttributeMaxDynamicSharedMemorySize, SMEM_BYTES);
    cudaFuncSetAttribute(k_gemm_mma<true, false, true, false>,
                         cudaFuncAttributeMaxDynamicSharedMemorySize, SMEM_BYTES);
    cudaFuncSetAttribute(k_gemm_mma<true, false, false, true>,
                         cudaFuncAttributeMaxDynamicSharedMemorySize, SMEM_BYTES);

    const int gemm_blocks = (NN + 127) / 128;        // 782
    const int edge_blocks = (NE + 255) / 256;        // 6250
    const int gath_blocks = (NN + 15) / 16;          // 6250

    // CSR build (edge structure constant within a launch)
    k_detect<<<1, 32>>>((const int*)ei);
    k_zero_deg<<<NB, 256>>>();
    k_hist<<<edge_blocks, 256>>>(ei);
    k_blocksum<<<NB, 256>>>();
    k_scanb<<<1, 512>>>();
    k_offsets<<<NB, 256>>>();
    k_fill<<<edge_blocks, 256>>>(ei);

    const float* hin = x;
    for (int l = 0; l < NLAYERS; ++l) {
        k_zero_stats<<<1, 128>>>();
        k_gather<<<gath_blocks, 256>>>((const float4*)hin, (float4*)agg);
        k_gemm_mma<false, true, false, false><<<gemm_blocks, 128, SMEM_BYTES>>>(
            agg, W1s + l * 4096, b1s + l * 64, z, nullptr, nullptr, nullptr);
        k_bn<<<1, 64>>>(gammas + l * 64, betas + l * 64);
        if (l < NLAYERS - 1) {
            k_gemm_mma<true, false, true, false><<<gemm_blocks, 128, SMEM_BYTES>>>(
                z, W2s + l * 4096, b2s + l * 64, h, nullptr, nullptr, nullptr);
            hin = h;
        } else {
            k_gemm_mma<true, false, false, true><<<gemm_blocks, 128, SMEM_BYTES>>>(
                z, W2s + l * 4096, b2s + l * 64, hout, Wd, bd, out);
            hin = hout;
        }
    }
}